// round 15
// baseline (speedup 1.0000x reference)
#include <cuda_runtime.h>
#include <cuda_fp16.h>

// out[b,o] = max_k min(x[b,k], w[k,o])  (STE forward == hard max-min)
// x: [B,512] f32 uniform[0,1), w: [512,512] f32, out f32. B = 1024.
//
// Candidate algorithm (R6 hot-loop shape): per b-row, tier-1 cands
// x >= 0.875, tier-2 [0.78,0.875) for certificate failures, exact scan
// last resort (any-distribution correctness).
//
// R15: deterministic K-split (fixes R14). Grid (B, 2): block (b,h) selects
// ONLY candidates with (k & 1) == h — a partition by k, immune to atomic
// ordering (R14 split positions in two independently-ordered lists and
// silently dropped ~25% of candidates). Halves each warp's serial
// batch-wait chain and doubles resident warps. Blocks combine via
// atomicMax on float bits (exact, order-independent for nonneg floats).
// Ladder under partition: tier-2 winner => true out < CUT1 => BOTH halves'
// tier-1 partials < CUT1 => both run tier-2 over their own subsets (union
// = all); same at CUT2 for the exact full scan (both run it, idempotent).

#define KDIM 512
#define ODIM 512
#define O2   256          // half2 pairs along o; packed w row = 128 uint2
#define NT   128          // thread owns outputs [4t, 4t+4)
#define CUT1 0.875f
#define CUT2 0.78f
#define EPS  1e-3f        // fp16 rounding margin for certificates
#define C1MAX 160         // per-half tier1 ~32 +- 5.7
#define C2MAX 160

__device__ __half2 g_wh[KDIM * O2];   // [k][o2]; row k at uint2 index k*128

// pack w -> fp16 AND zero-init out (poisoned to 0xAA before timing)
__global__ __launch_bounds__(256)
void packw_zero_kernel(const float* __restrict__ w, float* __restrict__ out)
{
    int i = blockIdx.x * blockDim.x + threadIdx.x;   // 65536
    float4 v = reinterpret_cast<const float4*>(w)[i];
    __half2 h0 = __floats2half2_rn(v.x, v.y);
    __half2 h1 = __floats2half2_rn(v.z, v.w);
    uint2 pk;
    pk.x = *reinterpret_cast<unsigned*>(&h0);
    pk.y = *reinterpret_cast<unsigned*>(&h1);
    reinterpret_cast<uint2*>(g_wh)[i] = pk;

    float4 z = make_float4(0.f, 0.f, 0.f, 0.f);
    reinterpret_cast<float4*>(out)[2 * i]     = z;   // 8 floats -> 1024*512 total
    reinterpret_cast<float4*>(out)[2 * i + 1] = z;
}

__global__ __launch_bounds__(NT)
void maxmin_kernel(const float* __restrict__ x,
                   const float* __restrict__ w,
                   float* __restrict__ out)
{
    __shared__ float xs[KDIM];
    __shared__ uint2 c1[C1MAX];       // {half2-splat(x) bits, k*128}
    __shared__ uint2 c2[C2MAX];
    __shared__ int   s_n1, s_n2, s_ovf;

    const int b    = blockIdx.x;
    const int half = blockIdx.y;      // k-parity this block owns
    const int tid  = threadIdx.x;     // owns outputs 4*tid .. 4*tid+3

    if (tid == 0) { s_n1 = 0; s_n2 = 0; s_ovf = 0; }
    // zero c1 so padded batches are harmless (min(0,w)=0 over nonneg data)
    c1[tid] = make_uint2(0u, 0u);
    if (tid + NT < C1MAX) c1[tid + NT] = make_uint2(0u, 0u);
    __syncthreads();

    // ---- stage x row (for fallback) + selection of THIS HALF's k subset ----
    {
        float4 v = reinterpret_cast<const float4*>(x + (size_t)b * KDIM)[tid];
        reinterpret_cast<float4*>(xs)[tid] = v;
        float e[4] = {v.x, v.y, v.z, v.w};
#pragma unroll
        for (int q = 0; q < 4; q++) {
            int k = tid * 4 + q;
            if ((k & 1) != half) continue;          // deterministic partition
            float xv = e[q];
            if (xv >= CUT2) {
                __half   h  = __float2half_rn(xv);
                __half2  h2 = __halves2half2(h, h);
                unsigned hb = *reinterpret_cast<const unsigned*>(&h2);
                if (xv >= CUT1) {
                    int p = atomicAdd(&s_n1, 1);
                    if (p < C1MAX) c1[p] = make_uint2(hb, (unsigned)(k * 128));
                    else           s_ovf = 1;
                } else {
                    int p = atomicAdd(&s_n2, 1);
                    if (p < C2MAX) c2[p] = make_uint2(hb, (unsigned)(k * 128));
                    else           s_ovf = 1;
                }
            }
        }
    }
    __syncthreads();

    const int cnt1 = s_n1;
    const int cnt2 = (s_n2 < C2MAX) ? s_n2 : C2MAX;
    const int ovf  = s_ovf;
    const int n1p  = (cnt1 + 7) & ~7;       // zero-padded, <= C1MAX

    const uint2* wu = reinterpret_cast<const uint2*>(g_wh);

    __half2 a0 = __float2half2_rn(0.0f);    // inputs >= 0: 0 is a safe -inf
    __half2 a1 = a0;

    if (!ovf) {
        // ---- tier-1 hot loop over this half's ~32 candidates (~4 batches) ----
        for (int t = 0; t < n1p; t += 8) {
            uint2    wv[8];
            unsigned xb[8];
#pragma unroll
            for (int u = 0; u < 8; u++) {
                uint2 c = c1[t + u];        // broadcast LDS.64
                xb[u] = c.x;
                wv[u] = wu[c.y + tid];      // LDG.64
            }
#pragma unroll
            for (int u = 0; u < 8; u++) {
                __half2 xv = *reinterpret_cast<__half2*>(&xb[u]);
                a0 = __hmax2(a0, __hmin2(xv, *reinterpret_cast<__half2*>(&wv[u].x)));
                a1 = __hmax2(a1, __hmin2(xv, *reinterpret_cast<__half2*>(&wv[u].y)));
            }
        }
    }

    float r[4];
    r[0] = __low2float(a0); r[1] = __high2float(a0);
    r[2] = __low2float(a1); r[3] = __high2float(a1);

    // ---- tier-2 extension over this half's subset ----
    // (true tier-2 winner forces BOTH halves' partials < CUT1, so every
    //  tier-2 candidate is examined by exactly the half that owns it)
    bool fail1 = false;
#pragma unroll
    for (int j = 0; j < 4; j++) fail1 |= (r[j] < CUT1 + EPS);

    if (!ovf && fail1) {
#pragma unroll 1
        for (int t = 0; t < cnt2; t++) {
            uint2 c = c2[t];
            uint2 wv = wu[c.y + tid];
            __half2 xv = *reinterpret_cast<__half2*>(&c.x);
            a0 = __hmax2(a0, __hmin2(xv, *reinterpret_cast<__half2*>(&wv.x)));
            a1 = __hmax2(a1, __hmin2(xv, *reinterpret_cast<__half2*>(&wv.y)));
        }
        r[0] = __low2float(a0); r[1] = __high2float(a0);
        r[2] = __low2float(a1); r[3] = __high2float(a1);
    }

    // ---- exact fp32 full scan (both halves run it when triggered) ----
#pragma unroll 1
    for (int j = 0; j < 4; j++) {
        if (ovf || r[j] < CUT2 + EPS) {
            int o = tid * 4 + j;
            float v = 0.0f;
#pragma unroll 1
            for (int k = 0; k < KDIM; k += 4) {
                float m0 = fminf(xs[k],     w[(size_t)(k)     * ODIM + o]);
                float m1 = fminf(xs[k + 1], w[(size_t)(k + 1) * ODIM + o]);
                float m2 = fminf(xs[k + 2], w[(size_t)(k + 2) * ODIM + o]);
                float m3 = fminf(xs[k + 3], w[(size_t)(k + 3) * ODIM + o]);
                v = fmaxf(v, fmaxf(fmaxf(m0, m1), fmaxf(m2, m3)));
            }
            r[j] = v;
        }
    }

    // ---- publish: REDG.MAX on float bits (exact for nonneg floats) ----
    int* ob = reinterpret_cast<int*>(out + (size_t)b * ODIM + tid * 4);
    atomicMax(ob + 0, __float_as_int(r[0]));
    atomicMax(ob + 1, __float_as_int(r[1]));
    atomicMax(ob + 2, __float_as_int(r[2]));
    atomicMax(ob + 3, __float_as_int(r[3]));
}

extern "C" void kernel_launch(void* const* d_in, const int* in_sizes, int n_in,
                              void* d_out, int out_size)
{
    const float* x = (const float*)d_in[0];   // [B, 512]
    const float* w = (const float*)d_in[1];   // [512, 512]
    float* out = (float*)d_out;

    int B = in_sizes[0] / KDIM;               // 1024

    packw_zero_kernel<<<256, 256>>>(w, out);  // pack w + zero out
    dim3 grid(B, 2);                          // 2048 blocks: k-parity halves
    maxmin_kernel<<<grid, NT>>>(x, w, out);
}

// round 16
// speedup vs baseline: 1.6483x; 1.6483x over previous
#include <cuda_runtime.h>
#include <cuda_fp16.h>

// out[b,o] = max_k min(x[b,k], w[k,o])  (STE forward == hard max-min)
// x: [B,512] f32 uniform[0,1), w: [512,512] f32, out f32. B = 1024.
//
// Candidate algorithm (R6 base = measured best, 12.1us main): per b-row,
// tier-1 cands x >= 0.875 (~64), tier-2 [0.78,0.875) for certificate
// failures (~3e-4 of outputs), exact fp32 scan last resort
// (any-distribution correctness).
//
// R16 = R6 with the tier-1 batch widened 8 -> 16: all 16 LDS+LDG issue
// before any compute, halving the warp's serial batch-wait chain (8 -> 4
// dependent gather waits), with no double-buffer copies (R12's failure)
// and no extra blocks (R15's failure). c1 zero-padded to a multiple of 16
// (zero candidates harmless: min(0,w)=0 over nonnegative data).

#define KDIM 512
#define ODIM 512
#define O2   256          // half2 pairs along o; packed w row = 128 uint2
#define NT   128          // thread owns outputs [4t, 4t+4)
#define CUT1 0.875f
#define CUT2 0.78f
#define EPS  1e-3f        // fp16 rounding margin for certificates
#define C1MAX 160         // multiple of 16; tier1 ~64 +- 7.5
#define C2MAX 160

__device__ __half2 g_wh[KDIM * O2];   // [k][o2]; row k at uint2 index k*128

__global__ __launch_bounds__(512)
void packw_kernel(const float* __restrict__ w)
{
    int i = blockIdx.x * blockDim.x + threadIdx.x;   // 65536 float4 units
    float4 v = reinterpret_cast<const float4*>(w)[i];
    __half2 h0 = __floats2half2_rn(v.x, v.y);
    __half2 h1 = __floats2half2_rn(v.z, v.w);
    uint2 pk;
    pk.x = *reinterpret_cast<unsigned*>(&h0);
    pk.y = *reinterpret_cast<unsigned*>(&h1);
    reinterpret_cast<uint2*>(g_wh)[i] = pk;
}

__global__ __launch_bounds__(NT)
void maxmin_kernel(const float* __restrict__ x,
                   const float* __restrict__ w,
                   float* __restrict__ out)
{
    __shared__ float xs[KDIM];
    __shared__ uint2 c1[C1MAX];       // {half2-splat(x) bits, k*128}
    __shared__ uint2 c2[C2MAX];
    __shared__ int   s_n1, s_n2, s_ovf;

    const int b   = blockIdx.x;
    const int tid = threadIdx.x;      // owns outputs 4*tid .. 4*tid+3

    if (tid == 0) { s_n1 = 0; s_n2 = 0; s_ovf = 0; }
    // zero c1 so zero-padded batches are harmless
    c1[tid] = make_uint2(0u, 0u);
    if (tid + NT < C1MAX) c1[tid + NT] = make_uint2(0u, 0u);
    __syncthreads();

    // ---- stage x row (fp32, for fallback) + threshold selection ----
    {
        float4 v = reinterpret_cast<const float4*>(x + (size_t)b * KDIM)[tid];
        reinterpret_cast<float4*>(xs)[tid] = v;
        float e[4] = {v.x, v.y, v.z, v.w};
#pragma unroll
        for (int q = 0; q < 4; q++) {
            float xv = e[q];
            if (xv >= CUT2) {
                int k = tid * 4 + q;
                __half   h  = __float2half_rn(xv);
                __half2  h2 = __halves2half2(h, h);
                unsigned hb = *reinterpret_cast<const unsigned*>(&h2);
                if (xv >= CUT1) {
                    int p = atomicAdd(&s_n1, 1);
                    if (p < C1MAX) c1[p] = make_uint2(hb, (unsigned)(k * 128));
                    else           s_ovf = 1;
                } else {
                    int p = atomicAdd(&s_n2, 1);
                    if (p < C2MAX) c2[p] = make_uint2(hb, (unsigned)(k * 128));
                    else           s_ovf = 1;
                }
            }
        }
    }
    __syncthreads();

    const int cnt1 = s_n1;
    const int cnt2 = (s_n2 < C2MAX) ? s_n2 : C2MAX;
    const int ovf  = s_ovf;
    const int n1p  = (cnt1 + 15) & ~15;     // zero-padded, <= C1MAX

    const uint2* wu = reinterpret_cast<const uint2*>(g_wh);

    __half2 a0 = __float2half2_rn(0.0f);    // inputs >= 0: 0 is a safe -inf
    __half2 a1 = a0;

    if (!ovf) {
        // ---- tier-1 hot loop: MLP=16 batches (4 serial waits total) ----
        for (int t = 0; t < n1p; t += 16) {
            uint2    wv[16];
            unsigned xb[16];
#pragma unroll
            for (int u = 0; u < 16; u++) {
                uint2 c = c1[t + u];        // broadcast LDS.64
                xb[u] = c.x;
                wv[u] = wu[c.y + tid];      // LDG.64 — 16 in flight
            }
#pragma unroll
            for (int u = 0; u < 16; u++) {
                __half2 xv = *reinterpret_cast<__half2*>(&xb[u]);
                a0 = __hmax2(a0, __hmin2(xv, *reinterpret_cast<__half2*>(&wv[u].x)));
                a1 = __hmax2(a1, __hmin2(xv, *reinterpret_cast<__half2*>(&wv[u].y)));
            }
        }
    }

    float r[4];
    r[0] = __low2float(a0); r[1] = __high2float(a0);
    r[2] = __low2float(a1); r[3] = __high2float(a1);

    // ---- tier-2 extension (rare; any of 4 outputs failing certificate) ----
    bool fail1 = false;
#pragma unroll
    for (int j = 0; j < 4; j++) fail1 |= (r[j] < CUT1 + EPS);

    if (!ovf && fail1) {
#pragma unroll 1
        for (int t = 0; t < cnt2; t++) {
            uint2 c = c2[t];
            uint2 wv = wu[c.y + tid];
            __half2 xv = *reinterpret_cast<__half2*>(&c.x);
            a0 = __hmax2(a0, __hmin2(xv, *reinterpret_cast<__half2*>(&wv.x)));
            a1 = __hmax2(a1, __hmin2(xv, *reinterpret_cast<__half2*>(&wv.y)));
        }
        r[0] = __low2float(a0); r[1] = __high2float(a0);
        r[2] = __low2float(a1); r[3] = __high2float(a1);
    }

    // ---- exact fp32 fallback (essentially never for uniform inputs) ----
#pragma unroll 1
    for (int j = 0; j < 4; j++) {
        if (ovf || r[j] < CUT2 + EPS) {
            int o = tid * 4 + j;
            float v = 0.0f;
#pragma unroll 1
            for (int k = 0; k < KDIM; k += 4) {
                float m0 = fminf(xs[k],     w[(size_t)(k)     * ODIM + o]);
                float m1 = fminf(xs[k + 1], w[(size_t)(k + 1) * ODIM + o]);
                float m2 = fminf(xs[k + 2], w[(size_t)(k + 2) * ODIM + o]);
                float m3 = fminf(xs[k + 3], w[(size_t)(k + 3) * ODIM + o]);
                v = fmaxf(v, fmaxf(fmaxf(m0, m1), fmaxf(m2, m3)));
            }
            r[j] = v;
        }
    }

    reinterpret_cast<float4*>(out + (size_t)b * ODIM)[tid] =
        make_float4(r[0], r[1], r[2], r[3]);
}

extern "C" void kernel_launch(void* const* d_in, const int* in_sizes, int n_in,
                              void* d_out, int out_size)
{
    const float* x = (const float*)d_in[0];   // [B, 512]
    const float* w = (const float*)d_in[1];   // [512, 512]
    float* out = (float*)d_out;

    int B = in_sizes[0] / KDIM;               // 1024

    packw_kernel<<<128, 512>>>(w);
    maxmin_kernel<<<B, NT>>>(x, w, out);
}